// round 1
// baseline (speedup 1.0000x reference)
#include <cuda_runtime.h>
#include <math.h>

#define TT 2048
#define BB 8192
#define NTOT (TT * BB)          // 16777216
#define GAMMA 0.99f
#define NSEG 32
#define SEGLEN 64               // NSEG * SEGLEN == TT
#define CPB 32                  // columns per block
#define MIN_VAR 1e-6
#define MIN_CLIP (-10.0f)
#define MAX_CLIP (10.0f)

__device__ double g_sum;
__device__ double g_sum2;
__device__ float  g_scale;

__global__ void rr_zero_kernel() {
    g_sum = 0.0;
    g_sum2 = 0.0;
}

// Each block: 32 columns x 32 segments (1024 threads).
// Warp = one segment across 32 consecutive columns -> fully coalesced 128B loads.
__global__ __launch_bounds__(1024, 1)
void rr_scan_kernel(const float* __restrict__ x,
                    const float* __restrict__ dn,
                    const float* __restrict__ ret) {
    const int tx    = threadIdx.x;
    const int col_l = tx & 31;
    const int seg   = tx >> 5;
    const int col   = blockIdx.x * CPB + col_l;
    const int t0    = seg * SEGLEN;

    const float* __restrict__ xp  = x  + t0 * BB + col;
    const float* __restrict__ dpm = dn + t0 * BB + col;

    // d_prev for the first step of this segment
    float dp = (seg == 0) ? 0.0f : dpm[-BB];

    // Affine composition r_end = A*r0 + Bv ; sums are quadratic forms in r0
    float A = 1.0f, Bv = 0.0f;
    float Sa = 0.0f, Sb = 0.0f, Saa = 0.0f, Sab = 0.0f, Sbb = 0.0f;

#pragma unroll 8
    for (int i = 0; i < SEGLEN; i++) {
        float xv = xp[i * BB];
        float a  = GAMMA * (1.0f - dp);
        dp = dpm[i * BB];              // d_prev for next iteration
        A  = A * a;
        Bv = fmaf(a, Bv, xv);
        Sa += A;
        Sb += Bv;
        Saa = fmaf(A,  A,  Saa);
        Sab = fmaf(A,  Bv, Sab);
        Sbb = fmaf(Bv, Bv, Sbb);
    }

    __shared__ float tup[NSEG][CPB][8];
    tup[seg][col_l][0] = A;
    tup[seg][col_l][1] = Bv;
    tup[seg][col_l][2] = Sa;
    tup[seg][col_l][3] = Sb;
    tup[seg][col_l][4] = Saa;
    tup[seg][col_l][5] = Sab;
    tup[seg][col_l][6] = Sbb;
    __syncthreads();

    // First warp: sequential combine of 32 segments per column (double precision),
    // then warp-reduce 32 column totals and two atomics per block.
    if (tx < CPB) {
        double r0   = (double)ret[blockIdx.x * CPB + tx];
        double sum  = 0.0;
        double sum2 = 0.0;
#pragma unroll
        for (int s = 0; s < NSEG; s++) {
            const float* q = tup[s][tx];
            double Ad  = q[0], Bd  = q[1];
            double Sad = q[2], Sbd = q[3];
            double Saad = q[4], Sabd = q[5], Sbbd = q[6];
            sum  += Sad * r0 + Sbd;
            sum2 += (Saad * r0 + 2.0 * Sabd) * r0 + Sbbd;
            r0 = Ad * r0 + Bd;
        }
#pragma unroll
        for (int off = 16; off > 0; off >>= 1) {
            sum  += __shfl_down_sync(0xffffffffu, sum,  off);
            sum2 += __shfl_down_sync(0xffffffffu, sum2, off);
        }
        if (tx == 0) {
            atomicAdd(&g_sum,  sum);
            atomicAdd(&g_sum2, sum2);
        }
    }
}

__global__ void rr_finalize_kernel(const float* __restrict__ mean_p,
                                   const float* __restrict__ var_p,
                                   const float* __restrict__ count_p) {
    const double N = (double)NTOT;
    double bm = g_sum / N;
    double bv = g_sum2 / N - bm * bm;
    if (bv < 0.0) bv = 0.0;

    double mean0  = (double)mean_p[0];
    double var0   = (double)var_p[0];
    double count0 = (double)count_p[0];

    double new_var;
    if (count0 == 0.0) {
        new_var = bv;
    } else {
        double delta = bm - mean0;
        double total = count0 + N;
        double m2 = var0 * count0 + bv * N + delta * delta * count0 * N / total;
        new_var = m2 / total;
    }
    double obs_var = new_var > MIN_VAR ? new_var : MIN_VAR;
    g_scale = (float)(1.0 / sqrt(obs_var));
}

__global__ __launch_bounds__(256)
void rr_norm_kernel(const float4* __restrict__ x4, float4* __restrict__ o4) {
    int i = blockIdx.x * blockDim.x + threadIdx.x;
    float s = g_scale;
    float4 v = x4[i];
    float4 r;
    r.x = fminf(MAX_CLIP, fmaxf(MIN_CLIP, v.x * s));
    r.y = fminf(MAX_CLIP, fmaxf(MIN_CLIP, v.y * s));
    r.z = fminf(MAX_CLIP, fmaxf(MIN_CLIP, v.z * s));
    r.w = fminf(MAX_CLIP, fmaxf(MIN_CLIP, v.w * s));
    o4[i] = r;
}

extern "C" void kernel_launch(void* const* d_in, const int* in_sizes, int n_in,
                              void* d_out, int out_size) {
    const float* x     = (const float*)d_in[0];
    const float* dones = (const float*)d_in[1];
    const float* ret   = (const float*)d_in[2];
    const float* mean  = (const float*)d_in[3];
    const float* var   = (const float*)d_in[4];
    const float* count = (const float*)d_in[5];
    float* out = (float*)d_out;

    rr_zero_kernel<<<1, 1>>>();
    rr_scan_kernel<<<BB / CPB, NSEG * CPB>>>(x, dones, ret);
    rr_finalize_kernel<<<1, 1>>>(mean, var, count);

    const int n4 = NTOT / 4;
    rr_norm_kernel<<<n4 / 256, 256>>>((const float4*)x, (float4*)out);
}